// round 10
// baseline (speedup 1.0000x reference)
#include <cuda_runtime.h>
#include <cstdint>

#define B_DIM 512
#define IN_DIM 512
#define OUT_DIM 1024
#define TM 32
#define TN 64
#define TK 32
#define NSPLIT 2
#define KSPL (IN_DIM / NSPLIT)                    // 256 k per split
#define NTILES ((B_DIM / TM) * (OUT_DIM / TN))    // 256 output tiles

// Tropical (min-plus) matmul: out[m, n] = min_k (x[m,k] + w[n,k])
// x: [512, 512], w: [1024, 512], out: [512, 1024], row-major fp32.
//
// K-split-2 with in-kernel ticket-fused combine:
//   grid (16,16,2) = 512 plain CTAs (~14 warps/SM for latency hiding; no
//   cluster placement constraints). Each CTA computes its half-K partial
//   and stores it to its own half of a static scratch buffer. A per-tile
//   ticket (atomicAdd after a release fence) tells the SECOND arriver to
//   acquire-fence, load the partner's partial (L2-resident), min with its
//   own register accumulators, write the final output, and reset the
//   ticket so graph replays start clean. First arriver just exits.
//
// CTA tile 32(m) x 64(n), 128 threads, 4x4 register tile per thread.
// Double-buffered XOR-swizzled k-major smem tiles (col = row ^ (k & 28)):
// conflict-free scalar STS and float4 LDS. One barrier per k-tile,
// register-prefetched global loads, scalar FADD/FMNMX math.

__device__ float g_part[NSPLIT][NTILES][TM][TN];   // 4 MB static scratch
__device__ unsigned int g_tick[NTILES];            // zeroed at load; self-resetting

__global__ __launch_bounds__(128, 4)
void tropical_mm_kernel(const float* __restrict__ x,
                        const float* __restrict__ w,
                        float* __restrict__ out)
{
    __shared__ float xs[2][TK][TM];   // xs[p][k][m ^ (k&28)]
    __shared__ float ws[2][TK][TN];   // ws[p][k][n ^ (k&28)]
    __shared__ unsigned int s_turn;

    const int tid = threadIdx.x;
    const int tx = tid & 15;      // n-group: 4 outputs -> 64
    const int ty = tid >> 4;      // m-group: 4 outputs -> 32
    const int n0 = blockIdx.x * TN;
    const int m0 = blockIdx.y * TM;
    const int kz = blockIdx.z;
    const int kb = kz * KSPL;
    const int tile = blockIdx.y * (OUT_DIM / TN) + blockIdx.x;

    // Cooperative-load coords (float4 granularity)
    const int lr = tid >> 3;         // 0..15
    const int lk = (tid & 7) << 2;   // 0,4,...,28

    const float* xg0 = &x[(m0 + lr) * IN_DIM + kb + lk];
    const float* wg0 = &w[(n0 + lr) * IN_DIM + kb + lk];

    const float INF = __int_as_float(0x7f800000);
    float acc[4][4];
#pragma unroll
    for (int i = 0; i < 4; i++)
#pragma unroll
        for (int j = 0; j < 4; j++) acc[i][j] = INF;

    // Prologue: first tile into registers
    float4 xa0 = *reinterpret_cast<const float4*>(xg0);
    float4 xa1 = *reinterpret_cast<const float4*>(xg0 + 16 * IN_DIM);
    float4 wa0 = *reinterpret_cast<const float4*>(wg0);
    float4 wa1 = *reinterpret_cast<const float4*>(wg0 + 16 * IN_DIM);
    float4 wa2 = *reinterpret_cast<const float4*>(wg0 + 32 * IN_DIM);
    float4 wa3 = *reinterpret_cast<const float4*>(wg0 + 48 * IN_DIM);

    int p = 0;
    for (int k0 = 0; k0 < KSPL; k0 += TK) {
        // STS current tile (swizzled, conflict-free). Columns computed as
        // (row ^ lk) directly — NO additive shortcuts (see R3 bug).
        {
            int x0c = (lr +  0) ^ lk;
            int x1c = (lr + 16) ^ lk;
#pragma unroll
            for (int j = 0; j < 4; j++) {
                xs[p][lk + j][x0c] = (&xa0.x)[j];
                xs[p][lk + j][x1c] = (&xa1.x)[j];
            }
            int w0c = (lr +  0) ^ lk;
            int w1c = (lr + 16) ^ lk;
            int w2c = (lr + 32) ^ lk;
            int w3c = (lr + 48) ^ lk;
#pragma unroll
            for (int j = 0; j < 4; j++) {
                ws[p][lk + j][w0c] = (&wa0.x)[j];
                ws[p][lk + j][w1c] = (&wa1.x)[j];
                ws[p][lk + j][w2c] = (&wa2.x)[j];
                ws[p][lk + j][w3c] = (&wa3.x)[j];
            }
        }
        __syncthreads();

        // Prefetch next tile (overlaps the 32-k compute loop)
        if (k0 + TK < KSPL) {
            xg0 += TK; wg0 += TK;
            xa0 = *reinterpret_cast<const float4*>(xg0);
            xa1 = *reinterpret_cast<const float4*>(xg0 + 16 * IN_DIM);
            wa0 = *reinterpret_cast<const float4*>(wg0);
            wa1 = *reinterpret_cast<const float4*>(wg0 + 16 * IN_DIM);
            wa2 = *reinterpret_cast<const float4*>(wg0 + 32 * IN_DIM);
            wa3 = *reinterpret_cast<const float4*>(wg0 + 48 * IN_DIM);
        }

        // Compute: 8 k-classes x 4 k each; base pointers computed once per
        // class, inner LDS are [Rbase + immediate]. Pure FADD + FMNMX.
#pragma unroll
        for (int i = 0; i < 8; i++) {
            const float* xp = &xs[p][i << 2][(ty << 2) ^ (i << 2)];
            const float* wp = &ws[p][i << 2][(tx << 2) ^ (i << 2)];
#pragma unroll
            for (int kk = 0; kk < 4; kk++) {
                float4 xv = *reinterpret_cast<const float4*>(xp + kk * TM);
                float4 wv = *reinterpret_cast<const float4*>(wp + kk * TN);
                float xm[4] = {xv.x, xv.y, xv.z, xv.w};
                float wn[4] = {wv.x, wv.y, wv.z, wv.w};
#pragma unroll
                for (int a = 0; a < 4; a++)
#pragma unroll
                    for (int b = 0; b < 4; b++)
                        acc[a][b] = fminf(acc[a][b], xm[a] + wn[b]);
            }
        }
        p ^= 1;
        // Single barrier per tile: nobody can overwrite buffer q before
        // passing the next tile's barrier, by which time all threads have
        // finished computing from q.
    }

    // ── Ticket-fused combine (disjoint per-split scratch halves) ──
    float* mine = &g_part[kz][tile][0][0];
#pragma unroll
    for (int i = 0; i < 4; i++) {
        float4 o = make_float4(acc[i][0], acc[i][1], acc[i][2], acc[i][3]);
        *reinterpret_cast<float4*>(&mine[((ty << 2) + i) * TN + (tx << 2)]) = o;
    }
    __syncthreads();                       // CTA-wide: partial fully stored
    if (tid == 0) {
        __threadfence();                   // release: partial visible first
        s_turn = atomicAdd(&g_tick[tile], 1u);
    }
    __syncthreads();

    if (s_turn == 1) {                     // second arriver: combine + write
        __threadfence();                   // acquire: see partner's stores
        const float* theirs = &g_part[1 - kz][tile][0][0];
#pragma unroll
        for (int i = 0; i < 4; i++) {
            float4 pv = *reinterpret_cast<const float4*>(
                &theirs[((ty << 2) + i) * TN + (tx << 2)]);
            float4 o = make_float4(fminf(acc[i][0], pv.x),
                                   fminf(acc[i][1], pv.y),
                                   fminf(acc[i][2], pv.z),
                                   fminf(acc[i][3], pv.w));
            *reinterpret_cast<float4*>(
                &out[(m0 + (ty << 2) + i) * OUT_DIM + n0 + (tx << 2)]) = o;
        }
        if (tid == 0) g_tick[tile] = 0u;   // reset for next graph replay
    }
}

extern "C" void kernel_launch(void* const* d_in, const int* in_sizes, int n_in,
                              void* d_out, int out_size)
{
    const float* x = (const float*)d_in[0];   // [512, 512]
    const float* w = (const float*)d_in[1];   // [1024, 512]
    float* out = (float*)d_out;               // [512, 1024]

    dim3 grid(OUT_DIM / TN, B_DIM / TM, NSPLIT);   // (16, 16, 2) = 512 CTAs
    tropical_mm_kernel<<<grid, 128>>>(x, w, out);
}

// round 11
// speedup vs baseline: 1.1949x; 1.1949x over previous
#include <cuda_runtime.h>
#include <cstdint>

#define B_DIM 512
#define IN_DIM 512
#define OUT_DIM 1024
#define TM 32
#define TN 64
#define TK 32
#define KSPL 256   // K per warp-group (half of IN_DIM)

// Tropical (min-plus) matmul: out[m, n] = min_k (x[m,k] + w[n,k])
// x: [512, 512], w: [1024, 512], out: [512, 1024], row-major fp32.
//
// Intra-CTA K-split: 256-thread CTA, two 128-thread groups compute the SAME
// 32x64 output tile over DIFFERENT K-halves (group g covers K[g*256,
// g*256+256)). Grid (16,16) = 256 CTAs x 8 warps = 2048 warps (~14/SM) for
// latency hiding. Cross-split reduction is in-CTA: group 1 parks its 16
// accumulators in a dead smem region (group 1's x-tile, exactly 8 KB),
// group 0 mins and writes the output. No scratch, no fences, no tail kernel.
//
// Per group: 4x4 register tile per thread, double-buffered XOR-swizzled
// k-major smem tiles (col = row ^ (k & 28)) -> conflict-free scalar STS and
// float4 LDS; one barrier per k-tile; register-prefetched global loads;
// packed add.rn.f32x2 adds (bit-identical to scalar FADD RN), FMNMX mins.

__device__ __forceinline__ unsigned long long pack2(float lo, float hi) {
    unsigned long long r;
    asm("mov.b64 %0, {%1, %2};" : "=l"(r) : "r"(__float_as_uint(lo)), "r"(__float_as_uint(hi)));
    return r;
}
__device__ __forceinline__ unsigned long long addf32x2(unsigned long long a, unsigned long long b) {
    unsigned long long r;
    asm("add.rn.f32x2 %0, %1, %2;" : "=l"(r) : "l"(a), "l"(b));
    return r;
}
__device__ __forceinline__ void unpack2(unsigned long long v, float& lo, float& hi) {
    uint32_t l, h;
    asm("mov.b64 {%0, %1}, %2;" : "=r"(l), "=r"(h) : "l"(v));
    lo = __uint_as_float(l);
    hi = __uint_as_float(h);
}

__global__ __launch_bounds__(256, 2)
void tropical_mm_kernel(const float* __restrict__ x,
                        const float* __restrict__ w,
                        float* __restrict__ out)
{
    // Per-group tiles: [group][buffer][k][col]
    __shared__ float xs[2][2][TK][TM];   // 2 x 8 KB
    __shared__ float ws[2][2][TK][TN];   // 2 x 16 KB

    const int tid    = threadIdx.x;
    const int group  = tid >> 7;         // 0 or 1 = K-half
    const int wg_tid = tid & 127;
    const int tx = wg_tid & 15;          // n-group: 4 outputs -> 64
    const int ty = wg_tid >> 4;          // m-group: 4 outputs -> 32
    const int n0 = blockIdx.x * TN;
    const int m0 = blockIdx.y * TM;
    const int kb = group * KSPL;

    // Cooperative-load coords (float4 granularity) within the group
    const int lr = wg_tid >> 3;          // 0..15
    const int lk = (wg_tid & 7) << 2;    // 0,4,...,28

    const float* xg0 = &x[(m0 + lr) * IN_DIM + kb + lk];
    const float* wg0 = &w[(n0 + lr) * IN_DIM + kb + lk];

    const float INF = __int_as_float(0x7f800000);
    float acc[4][4];
#pragma unroll
    for (int i = 0; i < 4; i++)
#pragma unroll
        for (int j = 0; j < 4; j++) acc[i][j] = INF;

    // Prologue: first tile into registers
    float4 xa0 = *reinterpret_cast<const float4*>(xg0);
    float4 xa1 = *reinterpret_cast<const float4*>(xg0 + 16 * IN_DIM);
    float4 wa0 = *reinterpret_cast<const float4*>(wg0);
    float4 wa1 = *reinterpret_cast<const float4*>(wg0 + 16 * IN_DIM);
    float4 wa2 = *reinterpret_cast<const float4*>(wg0 + 32 * IN_DIM);
    float4 wa3 = *reinterpret_cast<const float4*>(wg0 + 48 * IN_DIM);

    int p = 0;
    for (int k0 = 0; k0 < KSPL; k0 += TK) {
        // STS current tile (swizzled, conflict-free). Columns computed as
        // (row ^ lk) directly — NO additive shortcuts (see R3 bug).
        {
            int x0c = (lr +  0) ^ lk;
            int x1c = (lr + 16) ^ lk;
#pragma unroll
            for (int j = 0; j < 4; j++) {
                xs[group][p][lk + j][x0c] = (&xa0.x)[j];
                xs[group][p][lk + j][x1c] = (&xa1.x)[j];
            }
            int w0c = (lr +  0) ^ lk;
            int w1c = (lr + 16) ^ lk;
            int w2c = (lr + 32) ^ lk;
            int w3c = (lr + 48) ^ lk;
#pragma unroll
            for (int j = 0; j < 4; j++) {
                ws[group][p][lk + j][w0c] = (&wa0.x)[j];
                ws[group][p][lk + j][w1c] = (&wa1.x)[j];
                ws[group][p][lk + j][w2c] = (&wa2.x)[j];
                ws[group][p][lk + j][w3c] = (&wa3.x)[j];
            }
        }
        __syncthreads();

        // Prefetch next tile (overlaps the 32-k compute loop)
        if (k0 + TK < KSPL) {
            xg0 += TK; wg0 += TK;
            xa0 = *reinterpret_cast<const float4*>(xg0);
            xa1 = *reinterpret_cast<const float4*>(xg0 + 16 * IN_DIM);
            wa0 = *reinterpret_cast<const float4*>(wg0);
            wa1 = *reinterpret_cast<const float4*>(wg0 + 16 * IN_DIM);
            wa2 = *reinterpret_cast<const float4*>(wg0 + 32 * IN_DIM);
            wa3 = *reinterpret_cast<const float4*>(wg0 + 48 * IN_DIM);
        }

        // Compute: 8 k-classes x 4 k each; base pointers computed once per
        // class, inner LDS are [Rbase + immediate].
#pragma unroll
        for (int i = 0; i < 8; i++) {
            const float* xp = &xs[group][p][i << 2][(ty << 2) ^ (i << 2)];
            const float* wp = &ws[group][p][i << 2][(tx << 2) ^ (i << 2)];
#pragma unroll
            for (int kk = 0; kk < 4; kk++) {
                float4 xv = *reinterpret_cast<const float4*>(xp + kk * TM);
                float4 wv = *reinterpret_cast<const float4*>(wp + kk * TN);
                unsigned long long w01 = pack2(wv.x, wv.y);
                unsigned long long w23 = pack2(wv.z, wv.w);
#pragma unroll
                for (int a = 0; a < 4; a++) {
                    float xa = (&xv.x)[a];
                    unsigned long long xd = pack2(xa, xa);
                    unsigned long long s01 = addf32x2(xd, w01);
                    unsigned long long s23 = addf32x2(xd, w23);
                    float s0, s1, s2, s3;
                    unpack2(s01, s0, s1);
                    unpack2(s23, s2, s3);
                    acc[a][0] = fminf(acc[a][0], s0);
                    acc[a][1] = fminf(acc[a][1], s1);
                    acc[a][2] = fminf(acc[a][2], s2);
                    acc[a][3] = fminf(acc[a][3], s3);
                }
            }
        }
        p ^= 1;
        // Single barrier per tile: nobody can overwrite buffer q before
        // passing the next tile's barrier, by which time every thread has
        // finished computing from q.
    }

    // ── In-CTA cross-split reduction ─────────────────────────────────────
    // Reuse group 1's x-tile region (dead after the mainloop) as the
    // 16x128 handoff buffer: 16*128*4 = 8192 B == sizeof(xs[1]).
    float (*red)[128] = reinterpret_cast<float (*)[128]>(&xs[1][0][0][0]);

    __syncthreads();                     // everyone done reading xs[1]
    if (group == 1) {
#pragma unroll
        for (int i = 0; i < 4; i++)
#pragma unroll
            for (int j = 0; j < 4; j++)
                red[(i << 2) + j][wg_tid] = acc[i][j];
    }
    __syncthreads();                     // handoff visible

    if (group == 0) {
#pragma unroll
        for (int i = 0; i < 4; i++) {
#pragma unroll
            for (int j = 0; j < 4; j++)
                acc[i][j] = fminf(acc[i][j], red[(i << 2) + j][wg_tid]);
            float4 o = make_float4(acc[i][0], acc[i][1], acc[i][2], acc[i][3]);
            *reinterpret_cast<float4*>(
                &out[(m0 + (ty << 2) + i) * OUT_DIM + n0 + (tx << 2)]) = o;
        }
    }
}

extern "C" void kernel_launch(void* const* d_in, const int* in_sizes, int n_in,
                              void* d_out, int out_size)
{
    const float* x = (const float*)d_in[0];   // [512, 512]
    const float* w = (const float*)d_in[1];   // [1024, 512]
    float* out = (float*)d_out;               // [512, 1024]

    dim3 grid(OUT_DIM / TN, B_DIM / TM);      // (16, 16) = 256 CTAs x 256 thr
    tropical_mm_kernel<<<grid, 256>>>(x, w, out);
}